// round 15
// baseline (speedup 1.0000x reference)
#include <cuda_runtime.h>
#include <cuda_bf16.h>
#include <cuda_fp16.h>
#include <cuda_fp8.h>
#include <cstdint>

#define VOCAB 32000
#define DIM   2048
#define NTOK  8192
#define IGNORE_IDX (-100)

// Tile 128x256, 8 warps (2M x 4N), warp 64x64. Stage = BK 128 bytes, 4 stages.
// Persistent CTAs; mbarrier-decoupled pipeline (no block-wide sync in loop).
#define BM 128
#define BN 256
#define BK 128
#define STAGES 4
#define NITER (DIM / BK)                      // 16
#define NTILES ((NTOK / BM) * (VOCAB / BN))   // 8000
#define ROWB 144                              // 128B data + 16B pad
#define ASIZE (BM * ROWB)                     // 18432
#define STAGE_BYTES ((BM + BN) * ROWB)        // 55296
#define HDR 1024
#define SMEM_DYN (HDR + STAGES * STAGE_BYTES) // 222208

__device__ uint8_t g_W8[(size_t)VOCAB * DIM];   // e4m3(64*W)
__device__ uint8_t g_H8[(size_t)NTOK * DIM];    // e4m3(H)
__device__ float g_sumexp[NTOK];
__device__ float g_tgt[NTOK];

// ---------------------------------------------------------------------------
__device__ __forceinline__ uint32_t smem_u32(const void* p) {
    uint32_t a;
    asm("{ .reg .u64 t; cvta.to.shared.u64 t, %1; cvt.u32.u64 %0, t; }" : "=r"(a) : "l"(p));
    return a;
}
__device__ __forceinline__ void cp16(uint32_t dst, const void* src) {
    asm volatile("cp.async.cg.shared.global [%0], [%1], 16;" :: "r"(dst), "l"(src) : "memory");
}
__device__ __forceinline__ void mbar_init(uint32_t a, uint32_t cnt) {
    asm volatile("mbarrier.init.shared.b64 [%0], %1;" :: "r"(a), "r"(cnt) : "memory");
}
__device__ __forceinline__ void mbar_wait(uint32_t a, uint32_t ph) {
    asm volatile(
        "{\n\t.reg .pred P;\n\t"
        "WL_%=:\n\t"
        "mbarrier.try_wait.parity.acquire.cta.shared::cta.b64 P, [%0], %1, 0x989680;\n\t"
        "@P bra WD_%=;\n\t"
        "bra WL_%=;\n\t"
        "WD_%=:\n\t}"
        :: "r"(a), "r"(ph) : "memory");
}
__device__ __forceinline__ void mbar_arrive(uint32_t a) {
    asm volatile("mbarrier.arrive.shared.b64 _, [%0];" :: "r"(a) : "memory");
}
__device__ __forceinline__ void cp_arrive_noinc(uint32_t a) {
    asm volatile("cp.async.mbarrier.arrive.noinc.shared.b64 [%0];" :: "r"(a) : "memory");
}
__device__ __forceinline__ void ldsm4(uint32_t& r0, uint32_t& r1, uint32_t& r2, uint32_t& r3,
                                      uint32_t addr) {
    asm volatile("ldmatrix.sync.aligned.m8n8.x4.shared.b16 {%0,%1,%2,%3}, [%4];"
                 : "=r"(r0), "=r"(r1), "=r"(r2), "=r"(r3) : "r"(addr));
}
__device__ __forceinline__ void qmma_h(uint32_t* d, const uint32_t* a, const uint32_t* b) {
    asm("mma.sync.aligned.m16n8k32.row.col.f16.e4m3.e4m3.f16 "
        "{%0,%1}, {%2,%3,%4,%5}, {%6,%7}, {%0,%1};"
        : "+r"(d[0]), "+r"(d[1])
        : "r"(a[0]), "r"(a[1]), "r"(a[2]), "r"(a[3]), "r"(b[0]), "r"(b[1]));
}
// exp via f16x2: e = 2^(acc * S*log2e), both halves at once
__device__ __forceinline__ uint32_t exp2_h2(uint32_t acc_h2) {
    const uint32_t C = 0x25C525C5u;   // half2(0.0225372 ~= log2e/64)
    uint32_t t, e;
    asm("mul.rn.f16x2 %0, %1, %2;" : "=r"(t) : "r"(acc_h2), "r"(C));
    asm("ex2.approx.f16x2 %0, %1;" : "=r"(e) : "r"(t));
    return e;
}
// tile index -> (m0, n0): 8 groups of (8 M-tiles x 125 N-tiles), N-fast
__device__ __forceinline__ void tile_coords(int t, int& m0, int& n0) {
    const int grp = t / 1000;
    const int rem = t - grp * 1000;
    n0 = (rem >> 3) * BN;
    m0 = (grp * 8 + (rem & 7)) * BM;
}

// ---------------------------------------------------------------------------
__global__ void cvt_kernel(const float* __restrict__ in, int which, int n4, float scale) {
    int i = blockIdx.x * blockDim.x + threadIdx.x;
    if (i >= n4) return;
    uint8_t* out = which ? g_H8 : g_W8;
    float4 v = ((const float4*)in)[i];
    float2 xy = make_float2(v.x * scale, v.y * scale);
    float2 zw = make_float2(v.z * scale, v.w * scale);
    uint32_t lo = __nv_cvt_float2_to_fp8x2(xy, __NV_SATFINITE, __NV_E4M3);
    uint32_t hi = __nv_cvt_float2_to_fp8x2(zw, __NV_SATFINITE, __NV_E4M3);
    ((uint32_t*)out)[i] = lo | (hi << 16);
}

__global__ void zero_kernel() {
    int i = blockIdx.x * blockDim.x + threadIdx.x;
    if (i < NTOK) g_sumexp[i] = 0.0f;
}

// ---------------------------------------------------------------------------
// Persistent FP8 GEMM (f16 accum) + fused sum(exp(logit/64)).
// mbarrier pipeline: full[s] (256 cp.async arrivals), empty[s] (8 warp arrivals).
// ---------------------------------------------------------------------------
__global__ void __launch_bounds__(256, 1) gemm_lse_q8() {
    extern __shared__ uint8_t smem[];
    const uint32_t sb = smem_u32(smem);

    const int tid  = threadIdx.x;
    const int lane = tid & 31;
    const int warp = tid >> 5;
    const int wm   = warp >> 2;
    const int wn   = warp & 3;
    const int g    = lane >> 2;
    const int tig  = lane & 3;
    const int bid  = blockIdx.x;
    const int G    = gridDim.x;

    if (tid == 0) {
#pragma unroll
        for (int s = 0; s < STAGES; s++) {
            mbar_init(sb + 16 * s, 256);      // full[s]
            mbar_init(sb + 16 * s + 8, 8);    // empty[s]
        }
    }
    __syncthreads();

    // Per-thread cp.async slots: 12 chunks (4 A rows step 32, 8 B rows step 32)
    const int prow = tid >> 3;           // 0..31
    const int pch  = tid & 7;            // 0..7 (16B within 128B row)
    const uint32_t dstA = (uint32_t)(HDR + prow * ROWB + pch * 16);
    const uint32_t dstB = (uint32_t)(HDR + ASIZE + prow * ROWB + pch * 16);

    // ldmatrix offsets (stage-relative)
    uint32_t a_off[4], b_off[4];
#pragma unroll
    for (int i = 0; i < 4; i++) {
        a_off[i] = (uint32_t)(HDR + (wm * 64 + i * 16 + (lane & 15)) * ROWB + (lane >> 4) * 16);
        b_off[i] = (uint32_t)(HDR + ASIZE + (wn * 64 + i * 16 + (lane & 15)) * ROWB + (lane >> 4) * 16);
    }

    // Producer state (runs STAGES-1 chunks ahead); phase starts flipped
    int ptile = bid, pk = 0;
    const uint8_t* pA;
    const uint8_t* pB;
    {
        int m0p, n0p;
        tile_coords(ptile, m0p, n0p);
        pA = g_H8 + (size_t)(m0p + prow) * DIM + pch * 16;
        pB = g_W8 + (size_t)(n0p + prow) * DIM + pch * 16;
    }
    int pstage = 0, pphase = 1;
    int cstage = 0, cphase = 0;

#define PRODUCE()                                                             \
    do {                                                                      \
        if (ptile < NTILES) {                                                 \
            mbar_wait(sb + 16 * pstage + 8, pphase);                          \
            const uint32_t wd = sb + (uint32_t)pstage * STAGE_BYTES;          \
            cp16(wd + dstA, pA);                                              \
            cp16(wd + dstA + 32 * ROWB, pA + (size_t)(32 * DIM));             \
            cp16(wd + dstA + 64 * ROWB, pA + (size_t)(64 * DIM));             \
            cp16(wd + dstA + 96 * ROWB, pA + (size_t)(96 * DIM));             \
            cp16(wd + dstB, pB);                                              \
            cp16(wd + dstB + 32 * ROWB, pB + (size_t)(32 * DIM));             \
            cp16(wd + dstB + 64 * ROWB, pB + (size_t)(64 * DIM));             \
            cp16(wd + dstB + 96 * ROWB, pB + (size_t)(96 * DIM));             \
            cp16(wd + dstB + 128 * ROWB, pB + (size_t)(128 * DIM));           \
            cp16(wd + dstB + 160 * ROWB, pB + (size_t)(160 * DIM));           \
            cp16(wd + dstB + 192 * ROWB, pB + (size_t)(192 * DIM));           \
            cp16(wd + dstB + 224 * ROWB, pB + (size_t)(224 * DIM));           \
            cp_arrive_noinc(sb + 16 * pstage);                                \
            pA += BK; pB += BK;                                               \
            if (++pk == NITER) {                                              \
                pk = 0; ptile += G;                                           \
                if (ptile < NTILES) {                                         \
                    int m0p, n0p;                                             \
                    tile_coords(ptile, m0p, n0p);                             \
                    pA = g_H8 + (size_t)(m0p + prow) * DIM + pch * 16;        \
                    pB = g_W8 + (size_t)(n0p + prow) * DIM + pch * 16;        \
                }                                                             \
            }                                                                 \
        }                                                                     \
        if (++pstage == STAGES) { pstage = 0; pphase ^= 1; }                  \
    } while (0)

#define LOAD_FRAGS(hk)                                                        \
    do {                                                                      \
        const uint32_t hb = rd + (hk) * 32;                                   \
        _Pragma("unroll")                                                     \
        for (int i = 0; i < 4; i++)                                           \
            ldsm4(af[i][0], af[i][1], af[i][2], af[i][3], hb + a_off[i]);     \
        _Pragma("unroll")                                                     \
        for (int p = 0; p < 4; p++) {                                         \
            uint32_t r0, r1, r2, r3;                                          \
            ldsm4(r0, r1, r2, r3, hb + b_off[p]);                             \
            bf[2 * p][0] = r0; bf[2 * p + 1][0] = r1;                         \
            bf[2 * p][1] = r2; bf[2 * p + 1][1] = r3;                         \
        }                                                                     \
    } while (0)

#define DO_QMMAS()                                                            \
    do {                                                                      \
        _Pragma("unroll")                                                     \
        for (int i = 0; i < 4; i++)                                           \
            _Pragma("unroll")                                                 \
            for (int j = 0; j < 8; j++) qmma_h(acc[i][j], af[i], bf[j]);      \
    } while (0)

    // Prologue: fill STAGES-1 stages (empty-waits pass immediately, phase=1)
#pragma unroll
    for (int s = 0; s < STAGES - 1; s++) PRODUCE();

    uint32_t acc[4][8][2];
#pragma unroll
    for (int a = 0; a < 4; a++)
#pragma unroll
        for (int b = 0; b < 8; b++) { acc[a][b][0] = 0u; acc[a][b][1] = 0u; }

#pragma unroll 1
    for (int ct = bid; ct < NTILES; ct += G) {
#pragma unroll 1
        for (int kt = 0; kt < NITER; kt++) {
            mbar_wait(sb + 16 * cstage, cphase);
            const uint32_t rd = sb + (uint32_t)cstage * STAGE_BYTES;

            uint32_t af[4][4], bf[8][2];
            LOAD_FRAGS(0);
            DO_QMMAS();
            // Producer refill overlaps tensor drain of the QMMAs above
            PRODUCE();
            LOAD_FRAGS(1);
            DO_QMMAS();
            LOAD_FRAGS(2);
            DO_QMMAS();
            LOAD_FRAGS(3);
            // All reads from this stage done -> release it
            if (lane == 0) mbar_arrive(sb + 16 * cstage + 8);
            if (++cstage == STAGES) { cstage = 0; cphase ^= 1; }
            DO_QMMAS();
        }

        // ---- per-tile epilogue: f16x2 exp + direct global reduction ----
        int m0c, n0c;
        tile_coords(ct, m0c, n0c);
#pragma unroll
        for (int i = 0; i < 4; i++) {
            float p0 = 0.0f, p1 = 0.0f;
#pragma unroll
            for (int j = 0; j < 8; j++) {
                uint32_t e0 = exp2_h2(acc[i][j][0]);
                uint32_t e1 = exp2_h2(acc[i][j][1]);
                float2 f0 = __half22float2(*reinterpret_cast<__half2*>(&e0));
                float2 f1 = __half22float2(*reinterpret_cast<__half2*>(&e1));
                p0 += f0.x + f0.y;
                p1 += f1.x + f1.y;
                acc[i][j][0] = 0u; acc[i][j][1] = 0u;
            }
            p0 += __shfl_xor_sync(0xffffffffu, p0, 1);
            p0 += __shfl_xor_sync(0xffffffffu, p0, 2);
            p1 += __shfl_xor_sync(0xffffffffu, p1, 1);
            p1 += __shfl_xor_sync(0xffffffffu, p1, 2);
            if (tig == 0) {
                atomicAdd(&g_sumexp[m0c + wm * 64 + i * 16 + g], p0);
                atomicAdd(&g_sumexp[m0c + wm * 64 + i * 16 + g + 8], p1);
            }
        }
    }
#undef PRODUCE
#undef LOAD_FRAGS
#undef DO_QMMAS
}

// ---------------------------------------------------------------------------
// Target logit: exact fp32 dot(hidden[t], weight[clip(target[t])])
// ---------------------------------------------------------------------------
__global__ void tgt_kernel(const float* __restrict__ W, const float* __restrict__ H,
                           const long long* __restrict__ tg) {
    const int t = blockIdx.x;
    long long v = tg[t];
    int vi = (int)v;
    vi = vi < 0 ? 0 : (vi >= VOCAB ? VOCAB - 1 : vi);
    const float4* h = (const float4*)(H + (size_t)t * DIM);
    const float4* w = (const float4*)(W + (size_t)vi * DIM);
    float s = 0.0f;
    for (int k = threadIdx.x; k < DIM / 4; k += 256) {
        float4 a = h[k], b = w[k];
        s += a.x * b.x + a.y * b.y + a.z * b.z + a.w * b.w;
    }
#pragma unroll
    for (int o = 16; o; o >>= 1) s += __shfl_xor_sync(0xffffffffu, s, o);
    __shared__ float red[8];
    if ((threadIdx.x & 31) == 0) red[threadIdx.x >> 5] = s;
    __syncthreads();
    if (threadIdx.x == 0) {
        float tot = 0.0f;
#pragma unroll
        for (int i = 0; i < 8; i++) tot += red[i];
        g_tgt[t] = tot;
    }
}

// ---------------------------------------------------------------------------
__global__ void finalize_kernel(const long long* __restrict__ tg, float* __restrict__ out) {
    __shared__ float ssum[32];
    __shared__ int scnt[32];
    float s = 0.0f;
    int c = 0;
    for (int t = threadIdx.x; t < NTOK; t += blockDim.x) {
        long long v = tg[t];
        if (v != IGNORE_IDX) {
            s += logf(g_sumexp[t]) - g_tgt[t];
            c++;
        }
    }
#pragma unroll
    for (int o = 16; o; o >>= 1) {
        s += __shfl_xor_sync(0xffffffffu, s, o);
        c += __shfl_xor_sync(0xffffffffu, c, o);
    }
    if ((threadIdx.x & 31) == 0) {
        ssum[threadIdx.x >> 5] = s;
        scnt[threadIdx.x >> 5] = c;
    }
    __syncthreads();
    if (threadIdx.x < 32) {
        int nw = blockDim.x >> 5;
        s = (threadIdx.x < nw) ? ssum[threadIdx.x] : 0.0f;
        c = (threadIdx.x < nw) ? scnt[threadIdx.x] : 0;
#pragma unroll
        for (int o = 16; o; o >>= 1) {
            s += __shfl_xor_sync(0xffffffffu, s, o);
            c += __shfl_xor_sync(0xffffffffu, c, o);
        }
        if (threadIdx.x == 0) out[0] = (c > 0) ? (s / (float)c) : s;
    }
}

// ---------------------------------------------------------------------------
extern "C" void kernel_launch(void* const* d_in, const int* in_sizes, int n_in,
                              void* d_out, int out_size) {
    const float* weight = nullptr;
    const float* hidden = nullptr;
    const long long* targets = nullptr;
    for (int i = 0; i < n_in; i++) {
        if (in_sizes[i] == VOCAB * DIM)      weight  = (const float*)d_in[i];
        else if (in_sizes[i] == NTOK * DIM)  hidden  = (const float*)d_in[i];
        else if (in_sizes[i] == NTOK)        targets = (const long long*)d_in[i];
    }

    cudaFuncSetAttribute(gemm_lse_q8, cudaFuncAttributeMaxDynamicSharedMemorySize, SMEM_DYN);

    int dev = 0, sms = 148;
    cudaGetDevice(&dev);
    cudaDeviceGetAttribute(&sms, cudaDevAttrMultiProcessorCount, dev);

    const int n4w = VOCAB * DIM / 4;
    cvt_kernel<<<(n4w + 255) / 256, 256>>>(weight, 0, n4w, 64.0f);
    const int n4h = NTOK * DIM / 4;
    cvt_kernel<<<(n4h + 255) / 256, 256>>>(hidden, 1, n4h, 1.0f);
    zero_kernel<<<(NTOK + 1023) / 1024, 1024>>>();

    gemm_lse_q8<<<sms, 256, SMEM_DYN>>>();

    tgt_kernel<<<NTOK, 256>>>(weight, hidden, targets);
    finalize_kernel<<<1, 1024>>>(targets, (float*)d_out);
}

// round 16
// speedup vs baseline: 1.0990x; 1.0990x over previous
#include <cuda_runtime.h>
#include <cuda_bf16.h>
#include <cuda_fp16.h>
#include <cuda_fp8.h>
#include <cstdint>

#define VOCAB 32000
#define DIM   2048
#define NTOK  8192
#define IGNORE_IDX (-100)

// Tile 128x256, 8 warps (2M x 4N), warp 64x64, BK=64, 7 stages.
// Persistent CTAs; mbarrier-decoupled pipeline (no block-wide sync in loop).
#define BM 128
#define BN 256
#define BK 64
#define STAGES 7
#define NITER (DIM / BK)                      // 32
#define NTILES ((NTOK / BM) * (VOCAB / BN))   // 8000
#define ROWB 80
#define ASIZE (BM * ROWB)                     // 10240
#define STAGE_BYTES ((BM + BN) * ROWB)        // 30720
#define HDR 1024
#define SMEM_DYN (HDR + STAGES * STAGE_BYTES) // 216064

__device__ uint8_t g_W8[(size_t)VOCAB * DIM];   // e4m3(64*W)
__device__ uint8_t g_H8[(size_t)NTOK * DIM];    // e4m3(H)
__device__ float g_sumexp[NTOK];
__device__ float g_tgt[NTOK];

// ---------------------------------------------------------------------------
__device__ __forceinline__ uint32_t smem_u32(const void* p) {
    uint32_t a;
    asm("{ .reg .u64 t; cvta.to.shared.u64 t, %1; cvt.u32.u64 %0, t; }" : "=r"(a) : "l"(p));
    return a;
}
__device__ __forceinline__ void cp16(uint32_t dst, const void* src) {
    asm volatile("cp.async.cg.shared.global [%0], [%1], 16;" :: "r"(dst), "l"(src) : "memory");
}
__device__ __forceinline__ void mbar_init(uint32_t a, uint32_t cnt) {
    asm volatile("mbarrier.init.shared.b64 [%0], %1;" :: "r"(a), "r"(cnt) : "memory");
}
__device__ __forceinline__ void mbar_wait(uint32_t a, uint32_t ph) {
    asm volatile(
        "{\n\t.reg .pred P;\n\t"
        "WL_%=:\n\t"
        "mbarrier.try_wait.parity.acquire.cta.shared::cta.b64 P, [%0], %1, 0x989680;\n\t"
        "@P bra WD_%=;\n\t"
        "bra WL_%=;\n\t"
        "WD_%=:\n\t}"
        :: "r"(a), "r"(ph) : "memory");
}
__device__ __forceinline__ void mbar_arrive(uint32_t a) {
    asm volatile("mbarrier.arrive.shared.b64 _, [%0];" :: "r"(a) : "memory");
}
__device__ __forceinline__ void cp_arrive_noinc(uint32_t a) {
    asm volatile("cp.async.mbarrier.arrive.noinc.shared.b64 [%0];" :: "r"(a) : "memory");
}
__device__ __forceinline__ void ldsm4(uint32_t& r0, uint32_t& r1, uint32_t& r2, uint32_t& r3,
                                      uint32_t addr) {
    asm volatile("ldmatrix.sync.aligned.m8n8.x4.shared.b16 {%0,%1,%2,%3}, [%4];"
                 : "=r"(r0), "=r"(r1), "=r"(r2), "=r"(r3) : "r"(addr));
}
__device__ __forceinline__ void qmma_h(uint32_t* d, const uint32_t* a, const uint32_t* b) {
    asm("mma.sync.aligned.m16n8k32.row.col.f16.e4m3.e4m3.f16 "
        "{%0,%1}, {%2,%3,%4,%5}, {%6,%7}, {%0,%1};"
        : "+r"(d[0]), "+r"(d[1])
        : "r"(a[0]), "r"(a[1]), "r"(a[2]), "r"(a[3]), "r"(b[0]), "r"(b[1]));
}
// exp via f16x2: e = 2^(acc * log2e/64), both halves at once
__device__ __forceinline__ uint32_t exp2_h2(uint32_t acc_h2) {
    const uint32_t C = 0x25C525C5u;   // half2(0.0225372 ~= log2e/64)
    uint32_t t, e;
    asm("mul.rn.f16x2 %0, %1, %2;" : "=r"(t) : "r"(acc_h2), "r"(C));
    asm("ex2.approx.f16x2 %0, %1;" : "=r"(e) : "r"(t));
    return e;
}
// tile index -> (m0, n0): 8 groups of (8 M-tiles x 125 N-tiles), N-fast
__device__ __forceinline__ void tile_coords(int t, int& m0, int& n0) {
    const int grp = t / 1000;
    const int rem = t - grp * 1000;
    n0 = (rem >> 3) * BN;
    m0 = (grp * 8 + (rem & 7)) * BM;
}

// ---------------------------------------------------------------------------
__global__ void cvt_kernel(const float* __restrict__ in, int which, int n4, float scale) {
    int i = blockIdx.x * blockDim.x + threadIdx.x;
    if (i >= n4) return;
    uint8_t* out = which ? g_H8 : g_W8;
    float4 v = ((const float4*)in)[i];
    float2 xy = make_float2(v.x * scale, v.y * scale);
    float2 zw = make_float2(v.z * scale, v.w * scale);
    uint32_t lo = __nv_cvt_float2_to_fp8x2(xy, __NV_SATFINITE, __NV_E4M3);
    uint32_t hi = __nv_cvt_float2_to_fp8x2(zw, __NV_SATFINITE, __NV_E4M3);
    ((uint32_t*)out)[i] = lo | (hi << 16);
}

__global__ void zero_kernel() {
    int i = blockIdx.x * blockDim.x + threadIdx.x;
    if (i < NTOK) g_sumexp[i] = 0.0f;
}

// ---------------------------------------------------------------------------
// Persistent FP8 GEMM (f16 accum) + fused sum(exp(logit/64)).
// mbarrier pipeline: full[s] (256 cp.async arrivals), empty[s] (8 warp arrivals).
// ---------------------------------------------------------------------------
__global__ void __launch_bounds__(256, 1) gemm_lse_q8() {
    extern __shared__ uint8_t smem[];
    const uint32_t sb = smem_u32(smem);

    const int tid  = threadIdx.x;
    const int lane = tid & 31;
    const int warp = tid >> 5;
    const int wm   = warp >> 2;
    const int wn   = warp & 3;
    const int g    = lane >> 2;
    const int tig  = lane & 3;
    const int bid  = blockIdx.x;
    const int G    = gridDim.x;

    if (tid == 0) {
#pragma unroll
        for (int s = 0; s < STAGES; s++) {
            mbar_init(sb + 16 * s, 256);      // full[s]
            mbar_init(sb + 16 * s + 8, 8);    // empty[s]
        }
    }
    __syncthreads();

    // Per-thread cp.async slots
    const int arow = tid >> 2;
    const int ach  = tid & 3;
    const uint32_t dstA = (uint32_t)(HDR + arow * ROWB + ach * 16);
    const uint32_t dstB = (uint32_t)(HDR + ASIZE + arow * ROWB + ach * 16);

    // ldmatrix offsets (stage-relative, incl header)
    uint32_t a_off[4], b_off[4];
#pragma unroll
    for (int i = 0; i < 4; i++) {
        a_off[i] = (uint32_t)(HDR + (wm * 64 + i * 16 + (lane & 15)) * ROWB + (lane >> 4) * 16);
        b_off[i] = (uint32_t)(HDR + ASIZE + (wn * 64 + i * 16 + (lane & 15)) * ROWB + (lane >> 4) * 16);
    }

    // Producer state (runs STAGES-1 chunks ahead); phase starts flipped
    int ptile = bid, pk = 0;
    const uint8_t* pA;
    const uint8_t* pB;
    {
        int m0p, n0p;
        tile_coords(ptile, m0p, n0p);
        pA = g_H8 + (size_t)(m0p + arow) * DIM + ach * 16;
        pB = g_W8 + (size_t)(n0p + arow) * DIM + ach * 16;
    }
    int pstage = 0, pphase = 1;
    int cstage = 0, cphase = 0;

#define PRODUCE()                                                             \
    do {                                                                      \
        if (ptile < NTILES) {                                                 \
            mbar_wait(sb + 16 * pstage + 8, pphase);                          \
            const uint32_t wd = sb + (uint32_t)pstage * STAGE_BYTES;          \
            cp16(wd + dstA, pA);                                              \
            cp16(wd + dstA + 64 * ROWB, pA + (size_t)(64 * DIM));             \
            cp16(wd + dstB, pB);                                              \
            cp16(wd + dstB + 64 * ROWB, pB + (size_t)(64 * DIM));             \
            cp16(wd + dstB + 128 * ROWB, pB + (size_t)(128 * DIM));           \
            cp16(wd + dstB + 192 * ROWB, pB + (size_t)(192 * DIM));           \
            cp_arrive_noinc(sb + 16 * pstage);                                \
            pA += BK; pB += BK;                                               \
            if (++pk == NITER) {                                              \
                pk = 0; ptile += G;                                           \
                if (ptile < NTILES) {                                         \
                    int m0p, n0p;                                             \
                    tile_coords(ptile, m0p, n0p);                             \
                    pA = g_H8 + (size_t)(m0p + arow) * DIM + ach * 16;        \
                    pB = g_W8 + (size_t)(n0p + arow) * DIM + ach * 16;        \
                }                                                             \
            }                                                                 \
        }                                                                     \
        if (++pstage == STAGES) { pstage = 0; pphase ^= 1; }                  \
    } while (0)

    // Prologue: fill STAGES-1 stages (empty-waits pass immediately, phase=1)
#pragma unroll
    for (int s = 0; s < STAGES - 1; s++) PRODUCE();

    uint32_t acc[4][8][2];
#pragma unroll
    for (int a = 0; a < 4; a++)
#pragma unroll
        for (int b = 0; b < 8; b++) { acc[a][b][0] = 0u; acc[a][b][1] = 0u; }

#pragma unroll 1
    for (int ct = bid; ct < NTILES; ct += G) {
#pragma unroll 1
        for (int kt = 0; kt < NITER; kt++) {
            PRODUCE();

            // Wait data for this chunk (per-warp; no block rendezvous)
            mbar_wait(sb + 16 * cstage, cphase);
            const uint32_t rd = sb + (uint32_t)cstage * STAGE_BYTES;

            uint32_t a0[4][4], b0[8][2], a1[4][4], b1[8][2];
#pragma unroll
            for (int i = 0; i < 4; i++)
                ldsm4(a0[i][0], a0[i][1], a0[i][2], a0[i][3], rd + a_off[i]);
#pragma unroll
            for (int p = 0; p < 4; p++) {
                uint32_t r0, r1, r2, r3;
                ldsm4(r0, r1, r2, r3, rd + b_off[p]);
                b0[2 * p][0] = r0; b0[2 * p + 1][0] = r1;
                b0[2 * p][1] = r2; b0[2 * p + 1][1] = r3;
            }
#pragma unroll
            for (int i = 0; i < 4; i++)
                ldsm4(a1[i][0], a1[i][1], a1[i][2], a1[i][3], rd + 32 + a_off[i]);
#pragma unroll
            for (int p = 0; p < 4; p++) {
                uint32_t r0, r1, r2, r3;
                ldsm4(r0, r1, r2, r3, rd + 32 + b_off[p]);
                b1[2 * p][0] = r0; b1[2 * p + 1][0] = r1;
                b1[2 * p][1] = r2; b1[2 * p + 1][1] = r3;
            }

            // Fragments in registers -> release the stage (1 arrival per warp)
            if (lane == 0) mbar_arrive(sb + 16 * cstage + 8);
            if (++cstage == STAGES) { cstage = 0; cphase ^= 1; }

#pragma unroll
            for (int i = 0; i < 4; i++)
#pragma unroll
                for (int j = 0; j < 8; j++) qmma_h(acc[i][j], a0[i], b0[j]);
#pragma unroll
            for (int i = 0; i < 4; i++)
#pragma unroll
                for (int j = 0; j < 8; j++) qmma_h(acc[i][j], a1[i], b1[j]);
        }

        // ---- per-tile epilogue: f16x2 exp + direct global reduction ----
        int m0c, n0c;
        tile_coords(ct, m0c, n0c);
#pragma unroll
        for (int i = 0; i < 4; i++) {
            float p0 = 0.0f, p1 = 0.0f;
#pragma unroll
            for (int j = 0; j < 8; j++) {
                uint32_t e0 = exp2_h2(acc[i][j][0]);
                uint32_t e1 = exp2_h2(acc[i][j][1]);
                float2 f0 = __half22float2(*reinterpret_cast<__half2*>(&e0));
                float2 f1 = __half22float2(*reinterpret_cast<__half2*>(&e1));
                p0 += f0.x + f0.y;
                p1 += f1.x + f1.y;
                acc[i][j][0] = 0u; acc[i][j][1] = 0u;
            }
            p0 += __shfl_xor_sync(0xffffffffu, p0, 1);
            p0 += __shfl_xor_sync(0xffffffffu, p0, 2);
            p1 += __shfl_xor_sync(0xffffffffu, p1, 1);
            p1 += __shfl_xor_sync(0xffffffffu, p1, 2);
            if (tig == 0) {
                atomicAdd(&g_sumexp[m0c + wm * 64 + i * 16 + g], p0);
                atomicAdd(&g_sumexp[m0c + wm * 64 + i * 16 + g + 8], p1);
            }
        }
    }
#undef PRODUCE
}

// ---------------------------------------------------------------------------
// Target logit: exact fp32 dot(hidden[t], weight[clip(target[t])])
// ---------------------------------------------------------------------------
__global__ void tgt_kernel(const float* __restrict__ W, const float* __restrict__ H,
                           const long long* __restrict__ tg) {
    const int t = blockIdx.x;
    long long v = tg[t];
    int vi = (int)v;
    vi = vi < 0 ? 0 : (vi >= VOCAB ? VOCAB - 1 : vi);
    const float4* h = (const float4*)(H + (size_t)t * DIM);
    const float4* w = (const float4*)(W + (size_t)vi * DIM);
    float s = 0.0f;
    for (int k = threadIdx.x; k < DIM / 4; k += 256) {
        float4 a = h[k], b = w[k];
        s += a.x * b.x + a.y * b.y + a.z * b.z + a.w * b.w;
    }
#pragma unroll
    for (int o = 16; o; o >>= 1) s += __shfl_xor_sync(0xffffffffu, s, o);
    __shared__ float red[8];
    if ((threadIdx.x & 31) == 0) red[threadIdx.x >> 5] = s;
    __syncthreads();
    if (threadIdx.x == 0) {
        float tot = 0.0f;
#pragma unroll
        for (int i = 0; i < 8; i++) tot += red[i];
        g_tgt[t] = tot;
    }
}

// ---------------------------------------------------------------------------
__global__ void finalize_kernel(const long long* __restrict__ tg, float* __restrict__ out) {
    __shared__ float ssum[32];
    __shared__ int scnt[32];
    float s = 0.0f;
    int c = 0;
    for (int t = threadIdx.x; t < NTOK; t += blockDim.x) {
        long long v = tg[t];
        if (v != IGNORE_IDX) {
            s += logf(g_sumexp[t]) - g_tgt[t];
            c++;
        }
    }
#pragma unroll
    for (int o = 16; o; o >>= 1) {
        s += __shfl_xor_sync(0xffffffffu, s, o);
        c += __shfl_xor_sync(0xffffffffu, c, o);
    }
    if ((threadIdx.x & 31) == 0) {
        ssum[threadIdx.x >> 5] = s;
        scnt[threadIdx.x >> 5] = c;
    }
    __syncthreads();
    if (threadIdx.x < 32) {
        int nw = blockDim.x >> 5;
        s = (threadIdx.x < nw) ? ssum[threadIdx.x] : 0.0f;
        c = (threadIdx.x < nw) ? scnt[threadIdx.x] : 0;
#pragma unroll
        for (int o = 16; o; o >>= 1) {
            s += __shfl_xor_sync(0xffffffffu, s, o);
            c += __shfl_xor_sync(0xffffffffu, c, o);
        }
        if (threadIdx.x == 0) out[0] = (c > 0) ? (s / (float)c) : s;
    }
}

// ---------------------------------------------------------------------------
extern "C" void kernel_launch(void* const* d_in, const int* in_sizes, int n_in,
                              void* d_out, int out_size) {
    const float* weight = nullptr;
    const float* hidden = nullptr;
    const long long* targets = nullptr;
    for (int i = 0; i < n_in; i++) {
        if (in_sizes[i] == VOCAB * DIM)      weight  = (const float*)d_in[i];
        else if (in_sizes[i] == NTOK * DIM)  hidden  = (const float*)d_in[i];
        else if (in_sizes[i] == NTOK)        targets = (const long long*)d_in[i];
    }

    cudaFuncSetAttribute(gemm_lse_q8, cudaFuncAttributeMaxDynamicSharedMemorySize, SMEM_DYN);

    int dev = 0, sms = 148;
    cudaGetDevice(&dev);
    cudaDeviceGetAttribute(&sms, cudaDevAttrMultiProcessorCount, dev);

    const int n4w = VOCAB * DIM / 4;
    cvt_kernel<<<(n4w + 255) / 256, 256>>>(weight, 0, n4w, 64.0f);
    const int n4h = NTOK * DIM / 4;
    cvt_kernel<<<(n4h + 255) / 256, 256>>>(hidden, 1, n4h, 1.0f);
    zero_kernel<<<(NTOK + 1023) / 1024, 1024>>>();

    gemm_lse_q8<<<sms, 256, SMEM_DYN>>>();

    tgt_kernel<<<NTOK, 256>>>(weight, hidden, targets);
    finalize_kernel<<<1, 1024>>>(targets, (float*)d_out);
}